// round 1
// baseline (speedup 1.0000x reference)
#include <cuda_runtime.h>
#include <cstdint>

#define HH 512
#define WW 512
#define CCH 3
#define SS 2
#define AA 3
#define NB 8
#define BB 2
#define SKS 9
#define AKS 7

// Scratch (allocation-free rule: __device__ globals)
__device__ float g_tmpH[CCH * SS * HH * WW];   // horizontal sigma pass
__device__ float g_conv[CCH * SS * HH * WW];   // full sigma blur (6 maps)
__device__ float g_sig1d[SS * SKS];            // separable 1D sigma weights
__device__ float g_al1d[AA * AKS];             // separable 1D alpha weights

// ---------------------------------------------------------------------------
// Derive 1D separable weights = row sums of the 2D kernels (exact rank-1).
// ---------------------------------------------------------------------------
__global__ void k_init(const float* __restrict__ sig2d, const float* __restrict__ al2d) {
    int t = threadIdx.x;
    if (t < SS * SKS) {
        int s = t / SKS, i = t % SKS;
        float sum = 0.f;
        for (int j = 0; j < SKS; j++) sum += sig2d[(s * SKS + i) * SKS + j];
        g_sig1d[t] = sum;
    }
    if (t >= 32 && t < 32 + AA * AKS) {
        int u = t - 32;
        int a = u / AKS, i = u % AKS;
        float sum = 0.f;
        for (int j = 0; j < AKS; j++) sum += al2d[(a * AKS + i) * AKS + j];
        g_al1d[u] = sum;
    }
}

// ---------------------------------------------------------------------------
// K1a: clip + horizontal 9-tap sigma conv. One CTA per image row.
// Input layout HWC. Zero padding in x.
// ---------------------------------------------------------------------------
__global__ void k_hpass(const float* __restrict__ im) {
    __shared__ float row[WW * CCH];
    int y = blockIdx.x;
    const float* base = im + (size_t)y * WW * CCH;
    for (int i = threadIdx.x; i < WW * CCH; i += blockDim.x) {
        float v = base[i];
        row[i] = fminf(fmaxf(v, 0.f), 1.f);
    }
    __syncthreads();
    float w0[SKS], w1[SKS];
#pragma unroll
    for (int j = 0; j < SKS; j++) { w0[j] = g_sig1d[j]; w1[j] = g_sig1d[SKS + j]; }
    for (int c = 0; c < CCH; c++) {
        for (int x = threadIdx.x; x < WW; x += blockDim.x) {
            float a0 = 0.f, a1 = 0.f;
#pragma unroll
            for (int j = 0; j < SKS; j++) {
                int xx = x + j - SKS / 2;
                float v = (xx >= 0 && xx < WW) ? row[xx * CCH + c] : 0.f;
                a0 = fmaf(w0[j], v, a0);
                a1 = fmaf(w1[j], v, a1);
            }
            g_tmpH[(((size_t)c * SS + 0) * HH + y) * WW + x] = a0;
            g_tmpH[(((size_t)c * SS + 1) * HH + y) * WW + x] = a1;
        }
    }
}

// ---------------------------------------------------------------------------
// K1b: vertical 9-tap sigma conv. Fully coalesced, zero padding in y.
// ---------------------------------------------------------------------------
__global__ void k_vpass() {
    int t = blockIdx.x * blockDim.x + threadIdx.x;   // CCH*SS*HH*WW threads
    int x = t % WW;
    int y = (t / WW) % HH;
    int cs = t / (WW * HH);
    int s = cs % SS;
    float w[SKS];
#pragma unroll
    for (int j = 0; j < SKS; j++) w[j] = g_sig1d[s * SKS + j];
    float acc = 0.f;
#pragma unroll
    for (int j = 0; j < SKS; j++) {
        int yy = y + j - SKS / 2;
        float v = (yy >= 0 && yy < HH) ? g_tmpH[((size_t)cs * HH + yy) * WW + x] : 0.f;
        acc = fmaf(w[j], v, acc);
    }
    g_conv[t] = acc;
}

// ---------------------------------------------------------------------------
// K2: fused iso + separable 7-tap alpha conv + layout-transposed stores.
// One CTA per 16x16 tile per (c,s) map. Loops b (beta half) x a (alpha).
// ---------------------------------------------------------------------------
#define TH 16
#define TW 16
#define HALO 3
#define CTH (TH + 2 * HALO)     // 22
#define CTW (TW + 2 * HALO)     // 22
#define ISO_YS (CTW * NB + 8)   // 184: pad so 4y x 8bn warps are bank-conflict-free
#define TMP_YS (TW * NB + 8)    // 136: same trick for the tmp buffer

__global__ void k_loi(const float* __restrict__ centers,
                      const float* __restrict__ betas,
                      float* __restrict__ out) {
    __shared__ float s_conv[CTH * CTW];
    __shared__ float s_iso[CTH * ISO_YS];
    __shared__ float s_tmp[CTH * TMP_YS];

    int tid = threadIdx.x;
    int z = blockIdx.z;              // cs index: c = z/SS, s = z%SS
    int c = z / SS, s = z % SS;
    int gy0 = blockIdx.y * TH;
    int gx0 = blockIdx.x * TW;
    const float* convmap = g_conv + (size_t)z * HH * WW;

    // Load conv tile with halo 3; OOB -> sentinel so iso becomes exactly 0
    for (int i = tid; i < CTH * CTW; i += 256) {
        int ly = i / CTW, lx = i % CTW;
        int gy = gy0 + ly - HALO, gx = gx0 + lx - HALO;
        float v = -1e30f;
        if (gy >= 0 && gy < HH && gx >= 0 && gx < WW) v = convmap[(size_t)gy * WW + gx];
        s_conv[i] = v;
    }
    float cn[NB];
#pragma unroll
    for (int n = 0; n < NB; n++) cn[n] = __ldg(&centers[n]);
    __syncthreads();

    for (int b = 0; b < BB; b++) {
        float beta = __ldg(&betas[b]);
        float invb = 1.f / beta;
        float nrm = 0.3989422804014327f * invb;

        // iso generation: 8 bins for this beta, for all 22x22 positions
        for (int i = tid; i < CTH * CTW; i += 256) {
            int ly = i / CTW, lx = i % CTW;
            float v = s_conv[i];
            float* dst = &s_iso[ly * ISO_YS + lx * NB];
#pragma unroll
            for (int n = 0; n < NB; n++) {
                float t = (v - cn[n]) * invb;
                dst[n] = nrm * __expf(-0.5f * t * t);
            }
        }
        __syncthreads();

        for (int a = 0; a < AA; a++) {
            float wk[AKS];
#pragma unroll
            for (int j = 0; j < AKS; j++) wk[j] = g_al1d[a * AKS + j];

            // pass1: horizontal 7-tap on iso -> s_tmp. Thread = (y, n).
            if (tid < CTH * NB) {
                int y = tid >> 3, bn = tid & 7;
                float v[CTW];
#pragma unroll
                for (int x = 0; x < CTW; x++) v[x] = s_iso[y * ISO_YS + x * NB + bn];
#pragma unroll
                for (int x = 0; x < TW; x++) {
                    float acc = 0.f;
#pragma unroll
                    for (int j = 0; j < AKS; j++) acc = fmaf(wk[j], v[x + j], acc);
                    s_tmp[y * TMP_YS + x * NB + bn] = acc;
                }
            }
            __syncthreads();

            // pass2: vertical 7-tap + direct global stores.
            // Thread = (yh, x, n): 256 tasks, 8 output rows each.
            {
                int bn = tid & 7;
                int x = (tid >> 3) & 15;
                int yh = tid >> 7;
                int ybase = yh * (TH / 2);
                float v[TH / 2 + AKS - 1];
#pragma unroll
                for (int j = 0; j < TH / 2 + AKS - 1; j++)
                    v[j] = s_tmp[(ybase + j) * TMP_YS + x * NB + bn];

                size_t map = (((size_t)a * BB + b) * SS + s) * CCH + c;
                float* op = out + ((map * HH + (gy0 + ybase)) * (size_t)WW + (gx0 + x)) * NB + bn;
#pragma unroll
                for (int yy = 0; yy < TH / 2; yy++) {
                    float acc = 0.f;
#pragma unroll
                    for (int j = 0; j < AKS; j++) acc = fmaf(wk[j], v[yy + j], acc);
                    op[(size_t)yy * WW * NB] = acc;
                }
            }
            __syncthreads();
        }
    }
}

// ---------------------------------------------------------------------------
extern "C" void kernel_launch(void* const* d_in, const int* in_sizes, int n_in,
                              void* d_out, int out_size) {
    const float* im      = (const float*)d_in[0];   // (512,512,3)
    const float* sig2d   = (const float*)d_in[1];   // (2,9,9)
    const float* al2d    = (const float*)d_in[2];   // (3,7,7)
    const float* centers = (const float*)d_in[3];   // (8,)
    const float* betas   = (const float*)d_in[4];   // (2,)
    float* out = (float*)d_out;

    k_init<<<1, 64>>>(sig2d, al2d);
    k_hpass<<<HH, 256>>>(im);
    k_vpass<<<(CCH * SS * HH * WW) / 256, 256>>>();
    dim3 g(WW / TW, HH / TH, CCH * SS);
    k_loi<<<g, 256>>>(centers, betas, out);
}

// round 4
// speedup vs baseline: 1.0491x; 1.0491x over previous
#include <cuda_runtime.h>
#include <cstdint>

#define HH 512
#define WW 512
#define CCH 3
#define SS 2
#define AA 3
#define NB 8
#define BB 2
#define SKS 9
#define AKS 7

// Scratch (allocation-free rule: __device__ globals)
__device__ float g_tmpH[CCH * SS * HH * WW];   // horizontal sigma pass
__device__ float g_conv[CCH * SS * HH * WW];   // full sigma blur (6 maps)
__device__ float g_sig1d[SS * SKS];            // separable 1D sigma weights
__device__ float g_al1d[AA * AKS];             // separable 1D alpha weights

// ---------------------------------------------------------------------------
// Derive 1D separable weights = row sums of the 2D kernels (exact rank-1).
// ---------------------------------------------------------------------------
__global__ void k_init(const float* __restrict__ sig2d, const float* __restrict__ al2d) {
    int t = threadIdx.x;
    if (t < SS * SKS) {
        int s = t / SKS, i = t % SKS;
        float sum = 0.f;
        for (int j = 0; j < SKS; j++) sum += sig2d[(s * SKS + i) * SKS + j];
        g_sig1d[t] = sum;
    }
    if (t >= 32 && t < 32 + AA * AKS) {
        int u = t - 32;
        int a = u / AKS, i = u % AKS;
        float sum = 0.f;
        for (int j = 0; j < AKS; j++) sum += al2d[(a * AKS + i) * AKS + j];
        g_al1d[u] = sum;
    }
}

// ---------------------------------------------------------------------------
// K1a: clip + horizontal 9-tap sigma conv. One CTA per image row. Input HWC.
// ---------------------------------------------------------------------------
__global__ void k_hpass(const float* __restrict__ im) {
    __shared__ float row[WW * CCH];
    int y = blockIdx.x;
    const float* base = im + (size_t)y * WW * CCH;
    for (int i = threadIdx.x; i < WW * CCH; i += blockDim.x) {
        float v = base[i];
        row[i] = fminf(fmaxf(v, 0.f), 1.f);
    }
    __syncthreads();
    float w0[SKS], w1[SKS];
#pragma unroll
    for (int j = 0; j < SKS; j++) { w0[j] = g_sig1d[j]; w1[j] = g_sig1d[SKS + j]; }
    for (int c = 0; c < CCH; c++) {
        for (int x = threadIdx.x; x < WW; x += blockDim.x) {
            float a0 = 0.f, a1 = 0.f;
#pragma unroll
            for (int j = 0; j < SKS; j++) {
                int xx = x + j - SKS / 2;
                float v = (xx >= 0 && xx < WW) ? row[xx * CCH + c] : 0.f;
                a0 = fmaf(w0[j], v, a0);
                a1 = fmaf(w1[j], v, a1);
            }
            g_tmpH[(((size_t)c * SS + 0) * HH + y) * WW + x] = a0;
            g_tmpH[(((size_t)c * SS + 1) * HH + y) * WW + x] = a1;
        }
    }
}

// ---------------------------------------------------------------------------
// K1b: vertical 9-tap sigma conv. Fully coalesced, zero padding in y.
// ---------------------------------------------------------------------------
__global__ void k_vpass() {
    int t = blockIdx.x * blockDim.x + threadIdx.x;
    int x = t % WW;
    int y = (t / WW) % HH;
    int cs = t / (WW * HH);
    int s = cs % SS;
    float w[SKS];
#pragma unroll
    for (int j = 0; j < SKS; j++) w[j] = g_sig1d[s * SKS + j];
    float acc = 0.f;
#pragma unroll
    for (int j = 0; j < SKS; j++) {
        int yy = y + j - SKS / 2;
        float v = (yy >= 0 && yy < HH) ? g_tmpH[((size_t)cs * HH + yy) * WW + x] : 0.f;
        acc = fmaf(w[j], v, acc);
    }
    g_conv[t] = acc;
}

// ---------------------------------------------------------------------------
// Packed f32x2 helpers (sm_103a FFMA2 path — only reachable via PTX f32x2)
// ---------------------------------------------------------------------------
union F2U { float2 f; unsigned long long u; };
__device__ __forceinline__ float2 ffma2(float2 a, float2 b, float2 c) {
    F2U A, B, C, D; A.f = a; B.f = b; C.f = c;
    asm("fma.rn.f32x2 %0, %1, %2, %3;" : "=l"(D.u) : "l"(A.u), "l"(B.u), "l"(C.u));
    return D.f;
}
__device__ __forceinline__ float2 fmul2(float2 a, float2 b) {
    F2U A, B, D; A.f = a; B.f = b;
    asm("mul.rn.f32x2 %0, %1, %2;" : "=l"(D.u) : "l"(A.u), "l"(B.u));
    return D.f;
}

// ---------------------------------------------------------------------------
// K2: fused iso + separable 7-tap alpha conv, bin-paired float2 everywhere.
// One CTA per 16x16 tile per (c,s). Per beta: stage iso (1 exp per
// (pos,bin,beta)), then pipelined hconv(B, 176 thr) / vconv(C, 256 thr)
// with double-buffered tmp.
// ---------------------------------------------------------------------------
#define TS 16
#define HALO 3
#define CT 22          // TS + 2*HALO
#define ISO_RS 92      // float2 per iso row: 22*4 data + 4 pad (bank-safe)
#define TMP_RS 68      // float2 per tmp row: 16*4 data + 4 pad (bank-safe)

struct SMem {
    float  conv[CT * CT];
    float  cn[NB];
    float2 iso[CT * ISO_RS];        // [y][x*4+p] bins (2p,2p+1), one beta
    float2 tmp[2][CT * TMP_RS];     // double-buffered hconv result
};

__global__ __launch_bounds__(256, 3) void k_loi(const float* __restrict__ centers,
                                                const float* __restrict__ betas,
                                                float* __restrict__ out) {
    __shared__ SMem sm;
    int tid = threadIdx.x;
    int z = blockIdx.z;
    int c = z / SS, s = z % SS;
    int gy0 = blockIdx.y * TS;
    int gx0 = blockIdx.x * TS;
    const float* convmap = g_conv + (size_t)z * HH * WW;

    if (tid < NB) sm.cn[tid] = centers[tid];
    for (int i = tid; i < CT * CT; i += 256) {
        int ly = i / CT, lx = i - ly * CT;
        int gy = gy0 + ly - HALO, gx = gx0 + lx - HALO;
        sm.conv[i] = (gy >= 0 && gy < HH && gx >= 0 && gx < WW)
                     ? convmap[(size_t)gy * WW + gx] : -1e30f;   // exp -> 0
    }
    __syncthreads();

    // Phase A: iso field for beta b, all 22x22 positions, bins paired.
    auto phaseA = [&](int b) {
        float beta = __ldg(&betas[b]);
        float invb = 1.f / beta;
        float nrm = 0.3989422804014327f * invb;
        float kf = -0.5f * invb * invb;
        for (int i = tid; i < CT * CT * 4; i += 256) {
            int p = i & 3, pos = i >> 2;
            float cv = sm.conv[pos];
            float d0 = cv - sm.cn[2 * p];
            float d1 = cv - sm.cn[2 * p + 1];
            float2 e;
            e.x = nrm * __expf(kf * d0 * d0);
            e.y = nrm * __expf(kf * d1 * d1);
            int y = pos / CT, x = pos - y * CT;
            sm.iso[y * ISO_RS + x * 4 + p] = e;
        }
    };

    // Phase B: horizontal 7-tap on iso -> tmp[buf]. Thread=(xh,y,p), 176 act.
    auto phaseB = [&](int a, int buf) {
        if (tid < 176) {
            float2 wp[AKS];
#pragma unroll
            for (int j = 0; j < AKS; j++) {
                float w = __ldg(&g_al1d[a * AKS + j]);
                wp[j] = make_float2(w, w);
            }
            int xh = tid / 88;
            int r = tid - xh * 88;
            int y = r >> 2, p = r & 3;
            const float2* src = &sm.iso[y * ISO_RS + p];
            float2* dst = &sm.tmp[buf][y * TMP_RS + p];
            int xb = xh * 8;
            float2 win[AKS];
#pragma unroll
            for (int j = 0; j < 6; j++) win[j + 1] = src[(xb + j) * 4];
#pragma unroll
            for (int k = 6; k < 14; k++) {
#pragma unroll
                for (int j = 0; j < 6; j++) win[j] = win[j + 1];
                win[6] = src[(xb + k) * 4];
                float2 acc = fmul2(wp[0], win[0]);
#pragma unroll
                for (int j = 1; j < AKS; j++) acc = ffma2(wp[j], win[j], acc);
                dst[(xb + k - 6) * 4] = acc;
            }
        }
    };

    // Phase C: vertical 7-tap on tmp[buf] + coalesced float2 global stores.
    auto phaseC = [&](int a, int b, int buf) {
        float2 wp[AKS];
#pragma unroll
        for (int j = 0; j < AKS; j++) {
            float w = __ldg(&g_al1d[a * AKS + j]);
            wp[j] = make_float2(w, w);
        }
        int p = tid & 3, x = (tid >> 2) & 15, yq = tid >> 6;
        const float2* src = &sm.tmp[buf][(yq * 4) * TMP_RS + x * 4 + p];
        float2 v[10];
#pragma unroll
        for (int j = 0; j < 10; j++) v[j] = src[j * TMP_RS];
        size_t map = (((size_t)a * BB + b) * SS + s) * CCH + c;
        float2* op = (float2*)out +
                     ((map * HH + (gy0 + yq * 4)) * (size_t)WW + (gx0 + x)) * (NB / 2) + p;
#pragma unroll
        for (int yy = 0; yy < 4; yy++) {
            float2 acc = fmul2(wp[0], v[yy]);
#pragma unroll
            for (int j = 1; j < AKS; j++) acc = ffma2(wp[j], v[yy + j], acc);
            op[(size_t)yy * (WW * NB / 2)] = acc;
        }
    };

    phaseA(0);
    __syncthreads();
    for (int b = 0; b < BB; b++) {
        phaseB(0, 0);                 __syncthreads();
        phaseB(1, 1); phaseC(0, b, 0); __syncthreads();
        phaseB(2, 0); phaseC(1, b, 1); __syncthreads();
        phaseC(2, b, 0);
        if (b == 0) phaseA(1);        // prefetch next beta's iso
        __syncthreads();
    }
}

// ---------------------------------------------------------------------------
extern "C" void kernel_launch(void* const* d_in, const int* in_sizes, int n_in,
                              void* d_out, int out_size) {
    const float* im      = (const float*)d_in[0];   // (512,512,3)
    const float* sig2d   = (const float*)d_in[1];   // (2,9,9)
    const float* al2d    = (const float*)d_in[2];   // (3,7,7)
    const float* centers = (const float*)d_in[3];   // (8,)
    const float* betas   = (const float*)d_in[4];   // (2,)
    float* out = (float*)d_out;

    k_init<<<1, 64>>>(sig2d, al2d);
    k_hpass<<<HH, 256>>>(im);
    k_vpass<<<(CCH * SS * HH * WW) / 256, 256>>>();
    dim3 g(WW / TS, HH / TS, CCH * SS);
    k_loi<<<g, 256>>>(centers, betas, out);
}

// round 5
// speedup vs baseline: 1.1989x; 1.1428x over previous
#include <cuda_runtime.h>
#include <cstdint>

#define HH 512
#define WW 512
#define CCH 3
#define SS 2
#define AA 3
#define NB 8
#define BB 2
#define SKS 9
#define AKS 7

// Scratch (allocation-free rule: __device__ globals)
__device__ float g_tmpH[CCH * SS * HH * WW];   // horizontal sigma pass
__device__ float g_conv[CCH * SS * HH * WW];   // full sigma blur (6 maps)
__device__ float g_sig1d[SS * SKS];            // separable 1D sigma weights
__device__ float g_al1d[AA * AKS];             // separable 1D alpha weights

// ---------------------------------------------------------------------------
// Derive 1D separable weights = row sums of the 2D kernels (exact rank-1).
// ---------------------------------------------------------------------------
__global__ void k_init(const float* __restrict__ sig2d, const float* __restrict__ al2d) {
    int t = threadIdx.x;
    if (t < SS * SKS) {
        int s = t / SKS, i = t % SKS;
        float sum = 0.f;
        for (int j = 0; j < SKS; j++) sum += sig2d[(s * SKS + i) * SKS + j];
        g_sig1d[t] = sum;
    }
    if (t >= 32 && t < 32 + AA * AKS) {
        int u = t - 32;
        int a = u / AKS, i = u % AKS;
        float sum = 0.f;
        for (int j = 0; j < AKS; j++) sum += al2d[(a * AKS + i) * AKS + j];
        g_al1d[u] = sum;
    }
}

// ---------------------------------------------------------------------------
// K1a: clip + horizontal 9-tap sigma conv. One CTA per image row. Input HWC.
// ---------------------------------------------------------------------------
__global__ void k_hpass(const float* __restrict__ im) {
    __shared__ float row[WW * CCH];
    int y = blockIdx.x;
    const float* base = im + (size_t)y * WW * CCH;
    for (int i = threadIdx.x; i < WW * CCH; i += blockDim.x) {
        float v = base[i];
        row[i] = fminf(fmaxf(v, 0.f), 1.f);
    }
    __syncthreads();
    float w0[SKS], w1[SKS];
#pragma unroll
    for (int j = 0; j < SKS; j++) { w0[j] = g_sig1d[j]; w1[j] = g_sig1d[SKS + j]; }
    for (int c = 0; c < CCH; c++) {
        for (int x = threadIdx.x; x < WW; x += blockDim.x) {
            float a0 = 0.f, a1 = 0.f;
#pragma unroll
            for (int j = 0; j < SKS; j++) {
                int xx = x + j - SKS / 2;
                float v = (xx >= 0 && xx < WW) ? row[xx * CCH + c] : 0.f;
                a0 = fmaf(w0[j], v, a0);
                a1 = fmaf(w1[j], v, a1);
            }
            g_tmpH[(((size_t)c * SS + 0) * HH + y) * WW + x] = a0;
            g_tmpH[(((size_t)c * SS + 1) * HH + y) * WW + x] = a1;
        }
    }
}

// ---------------------------------------------------------------------------
// K1b: vertical 9-tap sigma conv. Fully coalesced, zero padding in y.
// ---------------------------------------------------------------------------
__global__ void k_vpass() {
    int t = blockIdx.x * blockDim.x + threadIdx.x;
    int x = t % WW;
    int y = (t / WW) % HH;
    int cs = t / (WW * HH);
    int s = cs % SS;
    float w[SKS];
#pragma unroll
    for (int j = 0; j < SKS; j++) w[j] = g_sig1d[s * SKS + j];
    float acc = 0.f;
#pragma unroll
    for (int j = 0; j < SKS; j++) {
        int yy = y + j - SKS / 2;
        float v = (yy >= 0 && yy < HH) ? g_tmpH[((size_t)cs * HH + yy) * WW + x] : 0.f;
        acc = fmaf(w[j], v, acc);
    }
    g_conv[t] = acc;
}

// ---------------------------------------------------------------------------
// Packed f32x2 helpers
// ---------------------------------------------------------------------------
union F2U { float2 f; unsigned long long u; };
__device__ __forceinline__ float2 ffma2(float2 a, float2 b, float2 c) {
    F2U A, B, C, D; A.f = a; B.f = b; C.f = c;
    asm("fma.rn.f32x2 %0, %1, %2, %3;" : "=l"(D.u) : "l"(A.u), "l"(B.u), "l"(C.u));
    return D.f;
}
__device__ __forceinline__ float2 fmul2(float2 a, float2 b) {
    F2U A, B, D; A.f = a; B.f = b;
    asm("mul.rn.f32x2 %0, %1, %2;" : "=l"(D.u) : "l"(A.u), "l"(B.u));
    return D.f;
}
__device__ __forceinline__ float2 fadd2(float2 a, float2 b) {
    F2U A, B, D; A.f = a; B.f = b;
    asm("add.rn.f32x2 %0, %1, %2;" : "=l"(D.u) : "l"(A.u), "l"(B.u));
    return D.f;
}

// ---------------------------------------------------------------------------
// K2 (streaming): thread = (x, binpair). Per input row: read 7-tap iso window
// from smem once, hconv for ALL 3 alphas, vertical conv in register rings
// acc[3][7]. iso staged per-row in a 4-slab ring (double-buffered 2-row
// batches -> one barrier per 2 rows). h and v 1D weights are identical
// (Gaussian rank-1 symmetry), 4 distinct taps each.
// ---------------------------------------------------------------------------
#define W_T 64
#define H_T 32
#define RIN 38           // H_T + 6 input rows
#define POS 70           // W_T + 6 iso positions per row
#define ISO_R 280        // POS*4 float2 per row slab

struct SMemL {
    float  conv[RIN * POS];      // 10640 B
    float2 iso[4 * ISO_R];       // 8960 B, slab = (row & 3)
};

__global__ __launch_bounds__(256, 2) void k_loi(const float* __restrict__ centers,
                                                const float* __restrict__ betas,
                                                float* __restrict__ out) {
    __shared__ SMemL sm;
    int tid = threadIdx.x;
    int x = tid >> 2, p = tid & 3;
    int z = blockIdx.z;
    int c = z / SS, s = z % SS;
    int gy0 = blockIdx.y * H_T;
    int gx0 = blockIdx.x * W_T;
    const float* convmap = g_conv + (size_t)z * HH * WW;

    // conv slab load (halo 3 all sides; OOB -> sentinel so iso == 0 exactly)
    for (int i = tid; i < RIN * POS; i += 256) {
        int r = i / POS, q = i - r * POS;
        int gy = gy0 + r - 3, gx = gx0 + q - 3;
        sm.conv[i] = (gy >= 0 && gy < HH && gx >= 0 && gx < WW)
                     ? __ldg(&convmap[(size_t)gy * WW + gx]) : -1e30f;
    }

    // per-thread bin centers (both bins of this thread's pair)
    float cn0 = __ldg(&centers[2 * p]);
    float cn1 = __ldg(&centers[2 * p + 1]);

    // weights: identical for h and v (row sums == col sums), symmetric: 4 taps
    float2 wk[AA][4];
#pragma unroll
    for (int a = 0; a < AA; a++)
#pragma unroll
        for (int k = 0; k < 4; k++) {
            float w = __ldg(&g_al1d[a * AKS + k]);
            wk[a][k] = make_float2(w, w);
        }
    __syncthreads();

#pragma unroll 1
    for (int b = 0; b < BB; b++) {
        float invb = 1.f / __ldg(&betas[b]);
        float nrm = 0.3989422804014327f * invb;
        float kf = -0.5f * invb * invb;

        // produce iso row R into slab (R & 3)
        auto produce = [&](int R) {
            float2* slab = &sm.iso[(R & 3) * ISO_R];
            {
                float cv = sm.conv[R * POS + (tid >> 2)];
                float d0 = cv - cn0, d1 = cv - cn1;
                float2 e;
                e.x = nrm * __expf(kf * d0 * d0);
                e.y = nrm * __expf(kf * d1 * d1);
                slab[tid] = e;
            }
            if (tid < (POS - W_T) * 4) {   // 24 tail tasks, same p
                float cv = sm.conv[R * POS + W_T + (tid >> 2)];
                float d0 = cv - cn0, d1 = cv - cn1;
                float2 e;
                e.x = nrm * __expf(kf * d0 * d0);
                e.y = nrm * __expf(kf * d1 * d1);
                slab[256 + tid] = e;
            }
        };

        produce(0); produce(1);
        __syncthreads();

        float2 acc[AA][7];
        float2* ob[AA];
#pragma unroll
        for (int a = 0; a < AA; a++)
            ob[a] = (float2*)out +
                    (size_t)(((a * BB + b) * SS + s) * CCH + c) * (HH * WW * (NB / 2));

        // stream 38 rows; inner unroll of 7 makes ring slots static
#pragma unroll 1
        for (int r7 = 0; r7 < 6; r7++) {
#pragma unroll
            for (int rr = 0; rr < 7; rr++) {
                int row = r7 * 7 + rr;
                if (row < RIN) {
                    // ---- consume: window + hconv (3 alphas) ----
                    const float2* src = &sm.iso[(row & 3) * ISO_R + x * 4 + p];
                    float2 v0 = src[0],  v1 = src[4],  v2 = src[8], v3 = src[12];
                    float2 v4 = src[16], v5 = src[20], v6 = src[24];
                    float2 s0 = fadd2(v0, v6), s1 = fadd2(v1, v5), s2 = fadd2(v2, v4);
                    float2 hv[AA];
#pragma unroll
                    for (int a = 0; a < AA; a++) {
                        float2 h = fmul2(wk[a][3], v3);
                        h = ffma2(wk[a][0], s0, h);
                        h = ffma2(wk[a][1], s1, h);
                        hv[a] = ffma2(wk[a][2], s2, h);
                    }
                    // ---- vertical ring update (static slots) ----
#pragma unroll
                    for (int t = 0; t < 7; t++) {
                        int y = row - t;
                        const int slot = ((rr - t) % 7 + 7) % 7;
                        const int wi = (t < 4) ? t : 6 - t;
                        bool ok = (y >= 0) && (y < H_T);
#pragma unroll
                        for (int a = 0; a < AA; a++) {
                            if (t == 0) { if (ok) acc[a][slot] = fmul2(wk[a][wi], hv[a]); }
                            else        { if (ok) acc[a][slot] = ffma2(wk[a][wi], hv[a], acc[a][slot]); }
                        }
                    }
                    // ---- store completed output row y = row - 6 ----
                    if (row >= 6) {
                        const int slot = (rr + 1) % 7;
                        size_t off = ((size_t)(gy0 + row - 6) * WW + gx0 + x) * (NB / 2) + p;
#pragma unroll
                        for (int a = 0; a < AA; a++) ob[a][off] = acc[a][slot];
                    }
                    // ---- pipelined iso production (next batch) ----
                    if ((row & 1) == 1) {
                        if (row + 1 < RIN) produce(row + 1);
                        if (row + 2 < RIN) produce(row + 2);
                    }
                }
                if (((r7 * 7 + rr) & 1) == 1) __syncthreads();
            }
        }
    }
}

// ---------------------------------------------------------------------------
extern "C" void kernel_launch(void* const* d_in, const int* in_sizes, int n_in,
                              void* d_out, int out_size) {
    const float* im      = (const float*)d_in[0];   // (512,512,3)
    const float* sig2d   = (const float*)d_in[1];   // (2,9,9)
    const float* al2d    = (const float*)d_in[2];   // (3,7,7)
    const float* centers = (const float*)d_in[3];   // (8,)
    const float* betas   = (const float*)d_in[4];   // (2,)
    float* out = (float*)d_out;

    k_init<<<1, 64>>>(sig2d, al2d);
    k_hpass<<<HH, 256>>>(im);
    k_vpass<<<(CCH * SS * HH * WW) / 256, 256>>>();
    dim3 g(WW / W_T, HH / H_T, CCH * SS);
    k_loi<<<g, 256>>>(centers, betas, out);
}

// round 7
// speedup vs baseline: 1.4258x; 1.1892x over previous
#include <cuda_runtime.h>
#include <cstdint>

#define HH 512
#define WW 512
#define CCH 3
#define SS 2
#define AA 3
#define NB 8
#define BB 2
#define SKS 9
#define AKS 7

// Scratch (allocation-free rule: __device__ globals)
__device__ float g_conv[CCH * SS * HH * WW];   // full sigma blur (6 maps)
__device__ float g_sig1d[SS * SKS];            // separable 1D sigma weights
__device__ float g_al1d[AA * AKS];             // separable 1D alpha weights

// ---------------------------------------------------------------------------
// Derive 1D separable weights = row sums of the 2D kernels (exact rank-1).
// ---------------------------------------------------------------------------
__global__ void k_init(const float* __restrict__ sig2d, const float* __restrict__ al2d) {
    int t = threadIdx.x;
    if (t < SS * SKS) {
        int s = t / SKS, i = t % SKS;
        float sum = 0.f;
        for (int j = 0; j < SKS; j++) sum += sig2d[(s * SKS + i) * SKS + j];
        g_sig1d[t] = sum;
    }
    if (t >= 32 && t < 32 + AA * AKS) {
        int u = t - 32;
        int a = u / AKS, i = u % AKS;
        float sum = 0.f;
        for (int j = 0; j < AKS; j++) sum += al2d[(a * AKS + i) * AKS + j];
        g_al1d[u] = sum;
    }
}

// ---------------------------------------------------------------------------
// Fused sigma blur: clip + separable 9-tap (both sigmas) per 32x32 tile.
// One CTA per (tile, channel). Symmetric 5-tap pairwise form.
// ---------------------------------------------------------------------------
#define STW 32
#define STH 32
#define SIN 40          // STH + 8

__global__ __launch_bounds__(256) void k_sigma(const float* __restrict__ im) {
    __shared__ float s_in[SIN][SIN];              // 6.4 KB
    __shared__ float s_ht[SS][SIN][STW + 1];      // 10.6 KB
    int tid = threadIdx.x;
    int c = blockIdx.z;
    int gy0 = blockIdx.y * STH, gx0 = blockIdx.x * STW;

    for (int i = tid; i < SIN * SIN; i += 256) {
        int r = i / SIN, q = i - r * SIN;
        int gy = gy0 + r - 4, gx = gx0 + q - 4;
        float v = 0.f;
        if (gy >= 0 && gy < HH && gx >= 0 && gx < WW) {
            v = __ldg(&im[((size_t)gy * WW + gx) * CCH + c]);
            v = fminf(fmaxf(v, 0.f), 1.f);
        }
        s_in[r][q] = v;
    }
    float w[SS][5];
#pragma unroll
    for (int s = 0; s < SS; s++)
#pragma unroll
        for (int k = 0; k < 5; k++) w[s][k] = __ldg(&g_sig1d[s * SKS + k]);
    __syncthreads();

    // horizontal pass (both sigmas)
    for (int i = tid; i < SIN * STW; i += 256) {
        int r = i / STW, x = i - r * STW;
        const float* row = &s_in[r][x];
        float p0 = row[0] + row[8], p1 = row[1] + row[7];
        float p2 = row[2] + row[6], p3 = row[3] + row[5];
        float m = row[4];
#pragma unroll
        for (int s = 0; s < SS; s++) {
            float acc = w[s][4] * m;
            acc = fmaf(w[s][0], p0, acc);
            acc = fmaf(w[s][1], p1, acc);
            acc = fmaf(w[s][2], p2, acc);
            acc = fmaf(w[s][3], p3, acc);
            s_ht[s][r][x] = acc;
        }
    }
    __syncthreads();

    // vertical pass + store
    for (int i = tid; i < STH * STW; i += 256) {
        int y = i / STW, x = i - y * STW;
#pragma unroll
        for (int s = 0; s < SS; s++) {
            const float* col = &s_ht[s][y][x];
            const int L = STW + 1;
            float p0 = col[0] + col[8 * L], p1 = col[1 * L] + col[7 * L];
            float p2 = col[2 * L] + col[6 * L], p3 = col[3 * L] + col[5 * L];
            float m = col[4 * L];
            float acc = w[s][4] * m;
            acc = fmaf(w[s][0], p0, acc);
            acc = fmaf(w[s][1], p1, acc);
            acc = fmaf(w[s][2], p2, acc);
            acc = fmaf(w[s][3], p3, acc);
            g_conv[(((size_t)c * SS + s) * HH + gy0 + y) * WW + gx0 + x] = acc;
        }
    }
}

// ---------------------------------------------------------------------------
// Packed f32x2 helpers
// ---------------------------------------------------------------------------
union F2U { float2 f; unsigned long long u; };
__device__ __forceinline__ float2 ffma2(float2 a, float2 b, float2 c) {
    F2U A, B, C, D; A.f = a; B.f = b; C.f = c;
    asm("fma.rn.f32x2 %0, %1, %2, %3;" : "=l"(D.u) : "l"(A.u), "l"(B.u), "l"(C.u));
    return D.f;
}
__device__ __forceinline__ float2 fmul2(float2 a, float2 b) {
    F2U A, B, D; A.f = a; B.f = b;
    asm("mul.rn.f32x2 %0, %1, %2;" : "=l"(D.u) : "l"(A.u), "l"(B.u));
    return D.f;
}
__device__ __forceinline__ float2 fadd2(float2 a, float2 b) {
    F2U A, B, D; A.f = a; B.f = b;
    asm("add.rn.f32x2 %0, %1, %2;" : "=l"(D.u) : "l"(A.u), "l"(B.u));
    return D.f;
}

// ---------------------------------------------------------------------------
// K2 (streaming, 3 CTAs/SM): thread = (x, binpair). Alphas 0,1 accumulate in
// register rings acc[2][7]; alpha 2 keeps its hconv history in a thread-
// private smem ring (no barriers needed) and gathers at output time.
// ---------------------------------------------------------------------------
#define W_T 64
#define H_T 32
#define RIN 38           // H_T + 6 input rows
#define POS 70           // W_T + 6 iso positions per row
#define ISO_R 280        // POS*4 float2 per row slab

struct SMemL {
    float  conv[RIN * POS];      // 10640 B
    float2 iso[4 * ISO_R];       // 8960 B, slab = (row & 3)
    float2 h2[7][256];           // 14336 B, thread-private alpha2 hconv ring
};

__global__ __launch_bounds__(256, 3) void k_loi(const float* __restrict__ centers,
                                                const float* __restrict__ betas,
                                                float* __restrict__ out) {
    __shared__ SMemL sm;
    int tid = threadIdx.x;
    int x = tid >> 2, p = tid & 3;
    int z = blockIdx.z;
    int c = z / SS, s = z % SS;
    int gy0 = blockIdx.y * H_T;
    int gx0 = blockIdx.x * W_T;
    const float* convmap = g_conv + (size_t)z * HH * WW;

    // conv slab load (halo 3 all sides; OOB -> sentinel so iso == 0 exactly)
    for (int i = tid; i < RIN * POS; i += 256) {
        int r = i / POS, q = i - r * POS;
        int gy = gy0 + r - 3, gx = gx0 + q - 3;
        sm.conv[i] = (gy >= 0 && gy < HH && gx >= 0 && gx < WW)
                     ? __ldg(&convmap[(size_t)gy * WW + gx]) : -1e30f;
    }

    float cn0 = __ldg(&centers[2 * p]);
    float cn1 = __ldg(&centers[2 * p + 1]);

    // h and v 1D weights identical (rank-1 symmetry), symmetric: 4 taps each
    float2 wk[AA][4];
#pragma unroll
    for (int a = 0; a < AA; a++)
#pragma unroll
        for (int k = 0; k < 4; k++) {
            float w = __ldg(&g_al1d[a * AKS + k]);
            wk[a][k] = make_float2(w, w);
        }
    __syncthreads();

    const size_t ASTR = (size_t)BB * SS * CCH * HH * WW * (NB / 2);  // float2

#pragma unroll 1
    for (int b = 0; b < BB; b++) {
        float invb = 1.f / __ldg(&betas[b]);
        float nrm = 0.3989422804014327f * invb;
        float kf = -0.5f * invb * invb;

        auto produce = [&](int R) {
            float2* slab = &sm.iso[(R & 3) * ISO_R];
            {
                float cv = sm.conv[R * POS + (tid >> 2)];
                float d0 = cv - cn0, d1 = cv - cn1;
                float2 e;
                e.x = nrm * __expf(kf * d0 * d0);
                e.y = nrm * __expf(kf * d1 * d1);
                slab[tid] = e;
            }
            if (tid < (POS - W_T) * 4) {
                float cv = sm.conv[R * POS + W_T + (tid >> 2)];
                float d0 = cv - cn0, d1 = cv - cn1;
                float2 e;
                e.x = nrm * __expf(kf * d0 * d0);
                e.y = nrm * __expf(kf * d1 * d1);
                slab[256 + tid] = e;
            }
        };

        produce(0); produce(1);
        __syncthreads();

        float2 acc[2][7];
        float2* outb = (float2*)out +
                       (size_t)((b * SS + s) * CCH + c) * (HH * WW * (NB / 2));

#pragma unroll 1
        for (int r7 = 0; r7 < 6; r7++) {
#pragma unroll
            for (int rr = 0; rr < 7; rr++) {
                int row = r7 * 7 + rr;
                if (row < RIN) {
                    // ---- hconv for all 3 alphas (symmetric pairwise) ----
                    const float2* src = &sm.iso[(row & 3) * ISO_R + x * 4 + p];
                    float2 t3 = src[12];
                    float2 hv0 = fmul2(wk[0][3], t3);
                    float2 hv1 = fmul2(wk[1][3], t3);
                    float2 hv2 = fmul2(wk[2][3], t3);
                    float2 ta = src[0], tb = src[24];
                    float2 sp = fadd2(ta, tb);
                    hv0 = ffma2(wk[0][0], sp, hv0);
                    hv1 = ffma2(wk[1][0], sp, hv1);
                    hv2 = ffma2(wk[2][0], sp, hv2);
                    ta = src[4]; tb = src[20]; sp = fadd2(ta, tb);
                    hv0 = ffma2(wk[0][1], sp, hv0);
                    hv1 = ffma2(wk[1][1], sp, hv1);
                    hv2 = ffma2(wk[2][1], sp, hv2);
                    ta = src[8]; tb = src[16]; sp = fadd2(ta, tb);
                    hv0 = ffma2(wk[0][2], sp, hv0);
                    hv1 = ffma2(wk[1][2], sp, hv1);
                    hv2 = ffma2(wk[2][2], sp, hv2);

                    // alpha2: stash hconv in thread-private smem ring
                    sm.h2[rr][tid] = hv2;

                    // alphas 0,1: vertical scatter rings (static slots)
#pragma unroll
                    for (int t = 0; t < 7; t++) {
                        int y = row - t;
                        const int slot = ((rr - t) % 7 + 7) % 7;
                        const int wi = (t < 4) ? t : 6 - t;
                        bool ok = (y >= 0) && (y < H_T);
                        if (t == 0) {
                            if (ok) {
                                acc[0][slot] = fmul2(wk[0][wi], hv0);
                                acc[1][slot] = fmul2(wk[1][wi], hv1);
                            }
                        } else {
                            if (ok) {
                                acc[0][slot] = ffma2(wk[0][wi], hv0, acc[0][slot]);
                                acc[1][slot] = ffma2(wk[1][wi], hv1, acc[1][slot]);
                            }
                        }
                    }

                    // ---- completed output row y = row - 6 ----
                    if (row >= 6) {
                        const int slot = (rr + 1) % 7;
                        // alpha2 vertical gather (symmetric pairwise)
                        float2 g0 = sm.h2[(rr + 1) % 7][tid];
                        float2 g1 = sm.h2[(rr + 2) % 7][tid];
                        float2 g2 = sm.h2[(rr + 3) % 7][tid];
                        float2 g3 = sm.h2[(rr + 4) % 7][tid];
                        float2 g4 = sm.h2[(rr + 5) % 7][tid];
                        float2 g5 = sm.h2[(rr + 6) % 7][tid];
                        float2 sA = fadd2(g0, hv2);
                        float2 sB = fadd2(g1, g5);
                        float2 sC = fadd2(g2, g4);
                        float2 o2 = fmul2(wk[2][3], g3);
                        o2 = ffma2(wk[2][0], sA, o2);
                        o2 = ffma2(wk[2][1], sB, o2);
                        o2 = ffma2(wk[2][2], sC, o2);

                        size_t off = ((size_t)(gy0 + row - 6) * WW + gx0 + x) * (NB / 2) + p;
                        outb[off] = acc[0][slot];
                        outb[off + ASTR] = acc[1][slot];
                        outb[off + 2 * ASTR] = o2;
                    }

                    // ---- pipelined iso production (next 2 rows) ----
                    if ((row & 1) == 1) {
                        if (row + 1 < RIN) produce(row + 1);
                        if (row + 2 < RIN) produce(row + 2);
                    }
                }
                if (((r7 * 7 + rr) & 1) == 1) __syncthreads();
            }
        }
    }
}

// ---------------------------------------------------------------------------
extern "C" void kernel_launch(void* const* d_in, const int* in_sizes, int n_in,
                              void* d_out, int out_size) {
    const float* im      = (const float*)d_in[0];   // (512,512,3)
    const float* sig2d   = (const float*)d_in[1];   // (2,9,9)
    const float* al2d    = (const float*)d_in[2];   // (3,7,7)
    const float* centers = (const float*)d_in[3];   // (8,)
    const float* betas   = (const float*)d_in[4];   // (2,)
    float* out = (float*)d_out;

    k_init<<<1, 64>>>(sig2d, al2d);
    dim3 gs(WW / STW, HH / STH, CCH);
    k_sigma<<<gs, 256>>>(im);
    dim3 g(WW / W_T, HH / H_T, CCH * SS);
    k_loi<<<g, 256>>>(centers, betas, out);
}